// round 14
// baseline (speedup 1.0000x reference)
#include <cuda_runtime.h>
#include <cstdint>

#define BATCH 16384
#define NB 8
#define BIN 512
#define BOUT 512
#define ROWSTRIDE 4096

#define BM 128
#define BN 128
#define BK 32
#define STAGES 3
#define THREADS 256
#define KITERS (BIN / BK)          // 16

#define A_STAGE_BYTES (BM * BK * 4)   // 16384
#define B_STAGE_BYTES (BN * BK * 4)   // 16384
#define SMEM_BYTES ((A_STAGE_BYTES + B_STAGE_BYTES) * STAGES)  // 98304

// W pre-rounded to tf32-RN (fp32 storage): no in-loop cvts.
__device__ float g_Wtf[NB * BOUT * BIN];

__device__ __forceinline__ uint32_t swz(uint32_t off) {
    return off ^ ((off >> 3) & 0x70);   // 128B-row xor swizzle
}

__device__ __forceinline__ void ldsm_x4(uint32_t* r, uint32_t addr) {
    asm volatile("ldmatrix.sync.aligned.m8n8.x4.shared.b16 {%0,%1,%2,%3}, [%4];"
                 : "=r"(r[0]), "=r"(r[1]), "=r"(r[2]), "=r"(r[3]) : "r"(addr));
}

__device__ __forceinline__ void cp16(uint32_t saddr, const void* g) {
    asm volatile("cp.async.cg.shared.global [%0], [%1], 16;" :: "r"(saddr), "l"(g));
}

__device__ __forceinline__ void mma_tf32(float* c, const uint32_t* a,
                                         uint32_t b0, uint32_t b1) {
    asm volatile(
        "mma.sync.aligned.m16n8k8.row.col.f32.tf32.tf32.f32 "
        "{%0,%1,%2,%3}, {%4,%5,%6,%7}, {%8,%9}, {%0,%1,%2,%3};"
        : "+f"(c[0]), "+f"(c[1]), "+f"(c[2]), "+f"(c[3])
        : "r"(a[0]), "r"(a[1]), "r"(a[2]), "r"(a[3]), "r"(b0), "r"(b1));
}

// mbarrier helpers
__device__ __forceinline__ void mbar_init(uint32_t addr, uint32_t cnt) {
    asm volatile("mbarrier.init.shared.b64 [%0], %1;" :: "r"(addr), "r"(cnt) : "memory");
}
__device__ __forceinline__ void mbar_arrive(uint32_t addr) {
    asm volatile("mbarrier.arrive.shared.b64 _, [%0];" :: "r"(addr) : "memory");
}
// arrives when this thread's prior cp.asyncs complete (count pre-included in init)
__device__ __forceinline__ void cp_arrive_noinc(uint32_t addr) {
    asm volatile("cp.async.mbarrier.arrive.noinc.shared.b64 [%0];" :: "r"(addr) : "memory");
}
__device__ __forceinline__ void mbar_wait(uint32_t addr, uint32_t parity) {
    uint32_t done;
    asm volatile("{\n\t.reg .pred p;\n\t"
        "mbarrier.try_wait.parity.acquire.cta.shared::cta.b64 p, [%1], %2;\n\t"
        "selp.b32 %0, 1, 0, p;\n\t}"
        : "=r"(done) : "r"(addr), "r"(parity) : "memory");
    if (!done) {
        asm volatile("{\n\t.reg .pred P1;\n\t"
            "W1_%=:\n\t"
            "mbarrier.try_wait.parity.acquire.cta.shared::cta.b64 P1, [%0], %1, 0x989680;\n\t"
            "@P1 bra.uni W2_%=;\n\t"
            "bra.uni W1_%=;\n\t"
            "W2_%=:\n\t}"
            :: "r"(addr), "r"(parity) : "memory");
    }
}

// ---- W pre-rounding: fp32 -> tf32-RN bits (fp32 storage) ----
__global__ void round_w_kernel(const float* __restrict__ W) {
    int i = (blockIdx.x * blockDim.x + threadIdx.x) * 4;
    float4 v = *reinterpret_cast<const float4*>(W + i);
    uint32_t r0, r1, r2, r3;
    asm("cvt.rna.tf32.f32 %0, %1;" : "=r"(r0) : "f"(v.x));
    asm("cvt.rna.tf32.f32 %0, %1;" : "=r"(r1) : "f"(v.y));
    asm("cvt.rna.tf32.f32 %0, %1;" : "=r"(r2) : "f"(v.z));
    asm("cvt.rna.tf32.f32 %0, %1;" : "=r"(r3) : "f"(v.w));
    float4 o = make_float4(__uint_as_float(r0), __uint_as_float(r1),
                           __uint_as_float(r2), __uint_as_float(r3));
    *reinterpret_cast<float4*>(g_Wtf + i) = o;
}

__global__ void __launch_bounds__(THREADS, 2)
block_linear_tf32_mbar(const float* __restrict__ x,
                       const float* __restrict__ bias,
                       float* __restrict__ out)
{
    __shared__ __align__(8) uint64_t s_full[STAGES], s_empty[STAGES];

    extern __shared__ uint8_t smem[];
    const uint32_t smem_u32 = (uint32_t)__cvta_generic_to_shared(smem);
    const uint32_t aBase = smem_u32;
    const uint32_t bBase = smem_u32 + STAGES * A_STAGE_BYTES;
    const uint32_t fullB  = (uint32_t)__cvta_generic_to_shared(s_full);
    const uint32_t emptyB = (uint32_t)__cvta_generic_to_shared(s_empty);

    const int n0 = blockIdx.x * BN;
    const int g  = blockIdx.y;
    const int m0 = blockIdx.z * BM;

    const int tid  = threadIdx.x;
    const int warp = tid >> 5;
    const int lane = tid & 31;
    const int grp  = lane >> 2;
    const int tig  = lane & 3;

    const int wm = (warp & 3) * 32;
    const int wn = (warp >> 2) * 64;

    const int lrow   = lane & 15;
    const int lchunk = (lane >> 4) * 16;

    if (tid < STAGES) {
        mbar_init(fullB  + tid * 8, THREADS);   // noinc cp-arrivals
        mbar_init(emptyB + tid * 8, THREADS);   // consumer arrives
    }
    __syncthreads();   // mbarrier init visible before any use (outside mainloop)

    const float* xg = x     + (size_t)m0 * ROWSTRIDE + (size_t)g * BIN;
    const float* Wg = g_Wtf + (size_t)g * (BOUT * BIN) + (size_t)n0 * BIN;

    float acc[2][8][4];
    #pragma unroll
    for (int i = 0; i < 2; i++)
        #pragma unroll
        for (int j = 0; j < 8; j++)
            #pragma unroll
            for (int c = 0; c < 4; c++) acc[i][j][c] = 0.0f;

    // producer cursor (parity starts flipped so first STAGES empty-waits pass)
    int ps = 0, pp = 1;
    auto produce = [&](int ki) {
        mbar_wait(emptyB + ps * 8, (uint32_t)pp);     // WAR: stage drained
        const float* xk = xg + ki * BK;
        const float* wk = Wg + ki * BK;
        uint32_t aS = aBase + ps * A_STAGE_BYTES;
        uint32_t bS = bBase + ps * B_STAGE_BYTES;
        #pragma unroll
        for (int it = 0; it < (BM * 8) / THREADS; it++) {
            int id  = tid + it * THREADS;
            int row = id >> 3, ch = id & 7;
            cp16(aS + swz(row * 128 + ch * 16),
                 xk + (size_t)row * ROWSTRIDE + ch * 4);
        }
        #pragma unroll
        for (int it = 0; it < (BN * 8) / THREADS; it++) {
            int id  = tid + it * THREADS;
            int row = id >> 3, ch = id & 7;
            cp16(bS + swz(row * 128 + ch * 16),
                 wk + (size_t)row * BIN + ch * 4);
        }
        cp_arrive_noinc(fullB + ps * 8);              // fires on cp completion
        if (++ps == STAGES) { ps = 0; pp ^= 1; }
    };

    // prologue: fill pipeline
    produce(0);
    produce(1);

    int cs = 0, cpar = 0;   // consumer cursor
    for (int ki = 0; ki < KITERS; ki++) {
        mbar_wait(fullB + cs * 8, (uint32_t)cpar);    // acquire: data visible

        const uint32_t aS = aBase + cs * A_STAGE_BYTES;
        const uint32_t bS = bBase + cs * B_STAGE_BYTES;

        #pragma unroll
        for (int ks = 0; ks < BK; ks += 8) {
            uint32_t a[2][4], b[4][4];
            #pragma unroll
            for (int mf = 0; mf < 2; mf++)
                ldsm_x4(a[mf], aS + swz((uint32_t)(wm + mf * 16 + lrow) * 128
                                        + ks * 4 + lchunk));
            #pragma unroll
            for (int q = 0; q < 4; q++)
                ldsm_x4(b[q], bS + swz((uint32_t)(wn + q * 16 + lrow) * 128
                                       + ks * 4 + lchunk));
            #pragma unroll
            for (int mf = 0; mf < 2; mf++) {
                #pragma unroll
                for (int q = 0; q < 4; q++) {
                    mma_tf32(acc[mf][2 * q],     a[mf], b[q][0], b[q][2]);
                    mma_tf32(acc[mf][2 * q + 1], a[mf], b[q][1], b[q][3]);
                }
            }
        }

        mbar_arrive(emptyB + cs * 8);                 // release: reads done
        if (++cs == STAGES) { cs = 0; cpar ^= 1; }

        if (ki + 2 < KITERS) produce(ki + 2);         // refill behind us
    }

    // ---- epilogue: bias add + float2 stores ----
    #pragma unroll
    for (int mf = 0; mf < 2; mf++) {
        #pragma unroll
        for (int nf = 0; nf < 8; nf++) {
            int col = n0 + wn + nf * 8 + tig * 2;
            float bv0 = bias[g * BOUT + col];
            float bv1 = bias[g * BOUT + col + 1];
            int r0 = m0 + wm + mf * 16 + grp;
            float* p0 = out + (size_t)r0 * (NB * BOUT) + (size_t)g * BOUT + col;
            float* p1 = p0 + (size_t)8 * (NB * BOUT);
            float2 v0 = make_float2(acc[mf][nf][0] + bv0, acc[mf][nf][1] + bv1);
            float2 v1 = make_float2(acc[mf][nf][2] + bv0, acc[mf][nf][3] + bv1);
            *reinterpret_cast<float2*>(p0) = v0;
            *reinterpret_cast<float2*>(p1) = v1;
        }
    }
}

extern "C" void kernel_launch(void* const* d_in, const int* in_sizes, int n_in,
                              void* d_out, int out_size)
{
    const float* x = (const float*)d_in[0];
    const float* W = (const float*)d_in[1];
    const float* b = (const float*)d_in[2];
    float* out     = (float*)d_out;

    cudaFuncSetAttribute(block_linear_tf32_mbar,
                         cudaFuncAttributeMaxDynamicSharedMemorySize,
                         SMEM_BYTES);

    round_w_kernel<<<(NB * BOUT * BIN) / (256 * 4), 256>>>(W);

    dim3 grid(BOUT / BN, NB, BATCH / BM);   // (4, 8, 128)
    block_linear_tf32_mbar<<<grid, THREADS, SMEM_BYTES>>>(x, b, out);
}